// round 13
// baseline (speedup 1.0000x reference)
#include <cuda_runtime.h>
#include <cstdint>
#include <cstddef>

#define B_ 8
#define N_ 2048
#define F_ 512
#define D_ 512

// ---------------- static device scratch (allocation-free rule) ----------------
__device__ float g_x[(size_t)B_ * N_ * F_];   // RNA-tf32-rounded x
__device__ float g_w[F_ * D_];                // RNA-tf32-rounded W
__device__ float g_t[(size_t)B_ * N_ * F_];   // t = a @ x, rounded to tf32
__device__ float g_mask[B_ * N_];

__device__ __forceinline__ uint32_t f2tf(float f) {
    uint32_t r;
    asm("cvt.rna.tf32.f32 %0, %1;" : "=r"(r) : "f"(f));
    return r;
}
__device__ __forceinline__ uint32_t smem_u32(const void* p) {
    uint32_t a;
    asm("{ .reg .u64 t; cvta.to.shared.u64 t, %1; cvt.u32.u64 %0, t; }" : "=r"(a) : "l"(p));
    return a;
}
__device__ __forceinline__ void cp16(uint32_t dst, const void* src) {
    asm volatile("cp.async.cg.shared.global [%0], [%1], 16;" :: "r"(dst), "l"(src));
}
__device__ __forceinline__ void cp_commit() {
    asm volatile("cp.async.commit_group;" ::: "memory");
}
__device__ __forceinline__ void cp_wait1() {
    asm volatile("cp.async.wait_group 1;" ::: "memory");
}

// ---------------- pre-pass kernels ----------------
// Round x to tf32 (RNA) and compute row mask in one pass. 128 threads/row.
__global__ void round_x_mask(const float* __restrict__ x, float* __restrict__ xo,
                             float* __restrict__ mask) {
    int row = blockIdx.x;
    int tid = threadIdx.x;                       // 0..127, F_/4 = 128 float4 per row
    const float4* xr = (const float4*)(x + (size_t)row * F_);
    float4 v = xr[tid];
    int nz = (v.x != 0.f) | (v.y != 0.f) | (v.z != 0.f) | (v.w != 0.f);
    ((uint4*)xo)[(size_t)row * 128 + tid] =
        make_uint4(f2tf(v.x), f2tf(v.y), f2tf(v.z), f2tf(v.w));
    nz = __syncthreads_or(nz);
    if (tid == 0) mask[row] = nz ? 1.0f : 0.0f;
}

__global__ void round_kernel(const float* __restrict__ in, float* __restrict__ out, size_t n4) {
    size_t i = (size_t)blockIdx.x * blockDim.x + threadIdx.x;
    if (i < n4) {
        float4 v = ((const float4*)in)[i];
        ((uint4*)out)[i] = make_uint4(f2tf(v.x), f2tf(v.y), f2tf(v.z), f2tf(v.w));
    }
}

// ---------------- tf32 mma.sync GEMM with cp.async 3-stage pipeline ----------------
// C[M,N] = A[M,K] @ B[K,N]; A,B,C row-major. CTA tile 128x128x32.
// 256 thr, 4x2 warps, warp tile 32x64 (m16n8k8).
// A smem row: 32 floats + 4 pad = 144B; B smem row: 128 floats + 4 pad = 528B.
constexpr int BM = 128, BN = 128, BKF = 32;
constexpr int STG = 3;
constexpr int AW = 36;                          // A words per row
constexpr int BW = 132;                         // B words per row
constexpr int A_BYTES = BM * AW * 4;            // 18432
constexpr int B_BYTES = BKF * BW * 4;           // 16896
constexpr int STAGE_BYTES = A_BYTES + B_BYTES;  // 35328
constexpr int STAGE_WORDS = STAGE_BYTES / 4;
constexpr int GSMEM = STG * STAGE_BYTES;        // 105984

template <bool EPI>
__global__ __launch_bounds__(256, 2)
void gemm_tf32(const float* __restrict__ A, const float* __restrict__ Bm,
               float* __restrict__ C, int NK, int lda, int ldb, int ldc,
               size_t sA, size_t sB, size_t sC, const float* __restrict__ mask) {
    extern __shared__ uint32_t smem[];
    const uint32_t sb = smem_u32(smem);

    const int tid = threadIdx.x;
    const int ln  = tid & 31;
    const int warp = tid >> 5;
    const int wm = warp >> 1;   // 0..3
    const int wn = warp & 1;    // 0..1
    const int row0 = blockIdx.y * BM;
    const int col0 = blockIdx.x * BN;
    const int z = blockIdx.z;

    const float* Ab = A + (size_t)z * sA + (size_t)row0 * lda;
    const float* Bb = Bm + (size_t)z * sB + col0;

    // per-thread fixed chunk coords
    const int ar = tid >> 1, ach = tid & 1;          // A: 128 rows x 8 chunks -> 4/thread (i*2 on ch)
    const int br = tid >> 3, bch = tid & 7;          // B: 32 rows x 32 chunks -> 4/thread (i*8 on ch)

    auto load_stage = [&](int j) {
        if (j < NK) {
            const uint32_t base = sb + (j % STG) * STAGE_BYTES;
            const float* ak = Ab + j * BKF;
            const float* bk = Bb + (size_t)j * BKF * ldb;
#pragma unroll
            for (int i = 0; i < 4; i++) {            // A chunks: (ar, ach + 2i)
                int ch = ach + 2 * i;
                cp16(base + ar * 144 + ch * 16, ak + (size_t)ar * lda + ch * 4);
            }
#pragma unroll
            for (int i = 0; i < 4; i++) {            // B chunks: (br, bch + 8i)
                int ch = bch + 8 * i;
                cp16(base + A_BYTES + br * 528 + ch * 16, bk + (size_t)br * ldb + ch * 4);
            }
        }
        cp_commit();
    };

    load_stage(0);
    load_stage(1);

    float acc[2][8][4] = {};
    uint32_t af[2][4], bf[8][2];

    for (int k0 = 0; k0 < NK; k0++) {
        cp_wait1();
        __syncthreads();
        load_stage(k0 + 2);

        const uint32_t* as = smem + (k0 % STG) * STAGE_WORDS;
        const uint32_t* bs = as + A_BYTES / 4;
#pragma unroll
        for (int kk = 0; kk < 4; kk++) {
            const int kb = kk * 8;
#pragma unroll
            for (int im = 0; im < 2; im++) {
                int r = wm * 32 + im * 16 + (ln >> 2);
                int c = kb + (ln & 3);
                af[im][0] = as[r * AW + c];
                af[im][1] = as[(r + 8) * AW + c];
                af[im][2] = as[r * AW + c + 4];
                af[im][3] = as[(r + 8) * AW + c + 4];
            }
#pragma unroll
            for (int in = 0; in < 8; in++) {
                int cn = wn * 64 + in * 8 + (ln >> 2);
                bf[in][0] = bs[(kb + (ln & 3)) * BW + cn];
                bf[in][1] = bs[(kb + (ln & 3) + 4) * BW + cn];
            }
#pragma unroll
            for (int im = 0; im < 2; im++)
#pragma unroll
                for (int in = 0; in < 8; in++) {
                    asm volatile(
                        "mma.sync.aligned.m16n8k8.row.col.f32.tf32.tf32.f32 "
                        "{%0,%1,%2,%3}, {%4,%5,%6,%7}, {%8,%9}, {%0,%1,%2,%3};"
                        : "+f"(acc[im][in][0]), "+f"(acc[im][in][1]),
                          "+f"(acc[im][in][2]), "+f"(acc[im][in][3])
                        : "r"(af[im][0]), "r"(af[im][1]), "r"(af[im][2]), "r"(af[im][3]),
                          "r"(bf[in][0]), "r"(bf[in][1]));
                }
        }
    }

    // Epilogue
    float* Cb = C + (size_t)z * sC;
#pragma unroll
    for (int im = 0; im < 2; im++) {
        int rbase = row0 + wm * 32 + im * 16 + (ln >> 2);
#pragma unroll
        for (int half = 0; half < 2; half++) {
            int r = rbase + half * 8;
            float mk = 1.0f;
            if (EPI) mk = mask[r];
            float* crow = Cb + (size_t)r * ldc;
#pragma unroll
            for (int in = 0; in < 8; in++) {
                int cc = col0 + wn * 64 + in * 8 + 2 * (ln & 3);
                float v0 = acc[im][in][half * 2 + 0];
                float v1 = acc[im][in][half * 2 + 1];
                if (EPI) {
                    v0 = fmaxf(v0, 0.f) * mk;
                    v1 = fmaxf(v1, 0.f) * mk;
                } else {  // round t to tf32 so GEMM2's raw cp.async loads are exact
                    v0 = __uint_as_float(f2tf(v0));
                    v1 = __uint_as_float(f2tf(v1));
                }
                *(float2*)(crow + cc) = make_float2(v0, v1);
            }
        }
    }
}

// ---------------- launch ----------------
extern "C" void kernel_launch(void* const* d_in, const int* in_sizes, int n_in,
                              void* d_out, int out_size) {
    const float *x = nullptr, *a = nullptr, *w = nullptr;
    for (int i = 0; i < n_in; i++) {
        if (in_sizes[i] == B_ * N_ * N_)      a = (const float*)d_in[i];
        else if (in_sizes[i] == F_ * D_)      w = (const float*)d_in[i];
        else                                  x = (const float*)d_in[i];
    }
    float* out = (float*)d_out;

    float *x_p, *w_p, *t_p, *mask_p;
    cudaGetSymbolAddress((void**)&x_p, g_x);
    cudaGetSymbolAddress((void**)&w_p, g_w);
    cudaGetSymbolAddress((void**)&t_p, g_t);
    cudaGetSymbolAddress((void**)&mask_p, g_mask);

    cudaFuncSetAttribute(gemm_tf32<false>, cudaFuncAttributeMaxDynamicSharedMemorySize, GSMEM);
    cudaFuncSetAttribute(gemm_tf32<true>,  cudaFuncAttributeMaxDynamicSharedMemorySize, GSMEM);

    // pre-passes: round x (+mask) and W to tf32-RNA; `a` is consumed raw
    // (HW tf32 MMA truncates its low mantissa bits; bias ~1.7e-4, within budget).
    round_x_mask<<<B_ * N_, 128>>>(x, x_p, mask_p);
    round_kernel<<<(F_ * D_ / 4 + 255) / 256, 256>>>(w, w_p, (size_t)F_ * D_ / 4);

    // GEMM1: t[b] = a[b] (2048x2048) @ x[b] (2048x512)
    gemm_tf32<false><<<dim3(F_ / BN, N_ / BM, B_), 256, GSMEM>>>(
        a, x_p, t_p, /*NK=*/N_ / BKF, /*lda=*/N_, /*ldb=*/F_, /*ldc=*/F_,
        (size_t)N_ * N_, (size_t)N_ * F_, (size_t)N_ * F_, nullptr);

    // GEMM2: out = relu(t (16384x512) @ W (512x512)) * mask
    gemm_tf32<true><<<dim3(D_ / BN, (B_ * N_) / BM, 1), 256, GSMEM>>>(
        t_p, w_p, out, /*NK=*/F_ / BKF, /*lda=*/F_, /*ldb=*/D_, /*ldc=*/D_,
        0, 0, 0, mask_p);
}